// round 15
// baseline (speedup 1.0000x reference)
#include <cuda_runtime.h>
#include <cuda_bf16.h>

#define SZ_OUT (64ull * 1024ull * 64ull)
#define STRIP 1028

// bf16 bias scratch: [b][q][k]
__device__ __align__(16) __nv_bfloat16 g_bias[1ull << 26];
// pre-split K/V in swizzled tile layout: idx = b<<16 | row<<6 | swizzled-col
__device__ __align__(16) __nv_bfloat16 g_Khi[1ull << 22], g_Klo[1ull << 22];
__device__ __align__(16) __nv_bfloat16 g_Vhi[1ull << 22], g_Vlo[1ull << 22];

// ===========================================================================
// bf16 split-GEMM helpers (mma.sync m16n8k16, 3-MMA fp32 emulation)
// ===========================================================================
__device__ __forceinline__ unsigned pk_bf2(float a, float b) {
    __nv_bfloat162 t = __floats2bfloat162_rn(a, b);
    return *reinterpret_cast<unsigned*>(&t);
}
__device__ __forceinline__ float2 bf2f(unsigned u) {
    __nv_bfloat162 h = *reinterpret_cast<__nv_bfloat162*>(&u);
    return __bfloat1622float2(h);
}

__device__ __forceinline__ void split_store(__nv_bfloat16* hi, __nv_bfloat16* lo,
                                            int r, int c, float4 v)
{
    int cb  = c >> 3;
    int off = (r << 6) + ((cb ^ (r & 7)) << 3) + (c & 7);
    float hx = __bfloat162float(__float2bfloat16(v.x));
    float hy = __bfloat162float(__float2bfloat16(v.y));
    float hz = __bfloat162float(__float2bfloat16(v.z));
    float hw = __bfloat162float(__float2bfloat16(v.w));
    *(uint2*)(hi + off) = make_uint2(pk_bf2(hx, hy), pk_bf2(hz, hw));
    *(uint2*)(lo + off) = make_uint2(pk_bf2(v.x - hx, v.y - hy),
                                     pk_bf2(v.z - hz, v.w - hw));
}

__device__ __forceinline__ void ldsm4(unsigned* r, unsigned addr) {
    asm volatile("ldmatrix.sync.aligned.m8n8.x4.shared.b16 {%0,%1,%2,%3}, [%4];"
                 : "=r"(r[0]), "=r"(r[1]), "=r"(r[2]), "=r"(r[3]) : "r"(addr));
}
__device__ __forceinline__ void ldsm4t(unsigned* r, unsigned addr) {
    asm volatile("ldmatrix.sync.aligned.m8n8.x4.trans.shared.b16 {%0,%1,%2,%3}, [%4];"
                 : "=r"(r[0]), "=r"(r[1]), "=r"(r[2]), "=r"(r[3]) : "r"(addr));
}
__device__ __forceinline__ void mma_bf16(float* c, const unsigned* a, const unsigned* b) {
    asm volatile("mma.sync.aligned.m16n8k16.row.col.f32.bf16.bf16.f32 "
                 "{%0,%1,%2,%3}, {%4,%5,%6,%7}, {%8,%9}, {%0,%1,%2,%3};"
                 : "+f"(c[0]), "+f"(c[1]), "+f"(c[2]), "+f"(c[3])
                 : "r"(a[0]), "r"(a[1]), "r"(a[2]), "r"(a[3]), "r"(b[0]), "r"(b[1]));
}

__device__ __forceinline__ unsigned sw_off(int r, int cb) {
    return (unsigned)((r << 7) + (((cb ^ (r & 7))) << 4));
}

// FFMA-pipe exp for t <= 0
__device__ __forceinline__ float fast_exp(float t) {
    float y = t * 1.4426950408889634f;
    int   n = __float2int_rn(y);
    float f = y - (float)n;
    float p = 1.3333558146428443e-3f;
    p = fmaf(p, f, 9.6181291076284772e-3f);
    p = fmaf(p, f, 5.5504108664821580e-2f);
    p = fmaf(p, f, 2.4022650695910071e-1f);
    p = fmaf(p, f, 6.9314718055994531e-1f);
    p = fmaf(p, f, 1.0f);
    int e = n + 127;
    e = e < 0 ? 0 : e;
    return p * __int_as_float(e << 23);
}

// ---------------------------------------------------------------------------
// Kernel 0: pre-split K and V to swizzled bf16 hi/lo. Grid (64 b, 8 rowblocks).
// ---------------------------------------------------------------------------
__global__ void __launch_bounds__(256) k_prep(const float* __restrict__ K,
                                              const float* __restrict__ V)
{
    const int b  = blockIdx.x;
    const int r0 = blockIdx.y << 7;
    const int tid = threadIdx.x;
    __nv_bfloat16* kh = g_Khi + ((size_t)b << 16);
    __nv_bfloat16* kl = g_Klo + ((size_t)b << 16);
    __nv_bfloat16* vh = g_Vhi + ((size_t)b << 16);
    __nv_bfloat16* vl = g_Vlo + ((size_t)b << 16);
    #pragma unroll
    for (int i = 0; i < 8; i++) {
        int f = tid + (i << 8);
        int r = r0 + (f >> 4), c = (f & 15) << 2;
        float4 kv = *(const float4*)&K[((size_t)b << 16) + ((size_t)r << 6) + c];
        float4 vv = *(const float4*)&V[((size_t)b << 16) + ((size_t)r << 6) + c];
        split_store(kh, kl, r, c, kv);
        split_store(vh, vl, r, c, vv);
    }
}

// ---------------------------------------------------------------------------
// Kernel 1: g_bias[b,q,k] = bf16( 0.125 * sum_d Q[b,q,d] * R_k[q,k,d] )
// (unchanged — control)
// ---------------------------------------------------------------------------
__global__ void __launch_bounds__(256) k_bias(const float* __restrict__ Q,
                                              const float* __restrict__ Rk)
{
    const int q  = blockIdx.y;
    const int k0 = blockIdx.x << 6;
    if (k0 > q) return;

    __shared__ __align__(16) __nv_bfloat16 aHi[4096], aLo[4096], bHi[4096], bLo[4096];
    const int tid = threadIdx.x;

    #pragma unroll
    for (int i = 0; i < 4; i++) {
        int f = tid + (i << 8); int r = f >> 4, c = (f & 15) << 2;
        float4 v = *(const float4*)&Q[((size_t)r << 16) + ((size_t)q << 6) + c];
        split_store(aHi, aLo, r, c, v);
    }
    #pragma unroll
    for (int i = 0; i < 4; i++) {
        int f = tid + (i << 8); int r = f >> 4, c = (f & 15) << 2;
        float4 v = *(const float4*)&Rk[(((size_t)q << 10) + (size_t)(k0 + r)) * 64 + c];
        split_store(bHi, bLo, r, c, v);
    }
    __syncthreads();

    const int warp = tid >> 5, lane = tid & 31;
    const int wm = (warp & 3) << 4;
    const int wn = (warp >> 2) << 5;

    const unsigned aH = (unsigned)__cvta_generic_to_shared(aHi);
    const unsigned aL = (unsigned)__cvta_generic_to_shared(aLo);
    const unsigned bH = (unsigned)__cvta_generic_to_shared(bHi);
    const unsigned bL = (unsigned)__cvta_generic_to_shared(bLo);

    const int arow = wm + (lane & 15);
    const int lhi  = lane >> 4;

    float c_[4][4] = {};

    #pragma unroll
    for (int ks = 0; ks < 4; ks++) {
        const int cb = (ks << 1) + lhi;
        unsigned a_hi[4], a_lo[4];
        ldsm4(a_hi, aH + sw_off(arow, cb));
        ldsm4(a_lo, aL + sw_off(arow, cb));
        unsigned b_hi[2][4], b_lo[2][4];
        #pragma unroll
        for (int h = 0; h < 2; h++) {
            int brow = wn + (h << 4) + (lane & 15);
            ldsm4(b_hi[h], bH + sw_off(brow, cb));
            ldsm4(b_lo[h], bL + sw_off(brow, cb));
        }
        #pragma unroll
        for (int j = 0; j < 4; j++) {
            const int h = j >> 1, o = j & 1;
            unsigned bh[2] = {b_hi[h][o], b_hi[h][o + 2]};
            unsigned bl[2] = {b_lo[h][o], b_lo[h][o + 2]};
            mma_bf16(c_[j], a_hi, bh);
            mma_bf16(c_[j], a_hi, bl);
            mma_bf16(c_[j], a_lo, bh);
        }
    }

    const int row0 = wm + (lane >> 2);
    const int coll = (lane & 3) << 1;
    #pragma unroll
    for (int j = 0; j < 4; j++) {
        int col = k0 + wn + (j << 3) + coll;
        *(unsigned*)&g_bias[((size_t)row0 << 20) + ((size_t)q << 10) + col] =
            pk_bf2(c_[j][0] * 0.125f, c_[j][1] * 0.125f);
        *(unsigned*)&g_bias[((size_t)(row0 + 8) << 20) + ((size_t)q << 10) + col] =
            pk_bf2(c_[j][2] * 0.125f, c_[j][3] * 0.125f);
    }
}

// ---------------------------------------------------------------------------
// Kernel 2: per (b, 32-row q strip). 512 threads, ~222 KB smem.
// phase1: mma scores (Q frags hoisted) + smem-staged bias epilogue
// phase2: softmax.  stage/convert: attn write + in-place split-P.
// phase4: out = P @ V from persistent split-P.
// ---------------------------------------------------------------------------
__global__ void __launch_bounds__(512) k_attn(const float* __restrict__ Q,
                                              float* attn,
                                              float* __restrict__ out)
{
    extern __shared__ float sm[];
    float* strip = sm;                                      // [32][1028] fp32
    __nv_bfloat16* pHi = (__nv_bfloat16*)sm;                // after convert
    __nv_bfloat16* pLo = (__nv_bfloat16*)sm + 32768;
    __nv_bfloat16* bufs = (__nv_bfloat16*)(sm + 32 * STRIP);
    __nv_bfloat16* qHi = bufs;
    __nv_bfloat16* qLo = bufs + 2048;
    __nv_bfloat16* kHi = bufs + 4096;
    __nv_bfloat16* kLo = bufs + 20480;
    __nv_bfloat16* vHi = bufs;                              // phase4 alias
    __nv_bfloat16* vLo = bufs + 8192;
    float* red = (float*)(bufs + 16384);                    // 6144 floats
    __nv_bfloat16* sBias = bufs + 36864;                    // [32][264]
    __shared__ float sInv[32];

    const int b   = blockIdx.x;
    const int q0  = (gridDim.y - 1 - blockIdx.y) << 5;
    const int tid = threadIdx.x;
    const int warp = tid >> 5, lane = tid & 31, lhi = lane >> 4;

    {
        int r = tid >> 4, c = (tid & 15) << 2;
        float4 v = *(const float4*)&Q[((size_t)b << 16) + ((size_t)(q0 + r) << 6) + c];
        split_store(qHi, qLo, r, c, v);
    }
    __syncthreads();

    const unsigned qH = (unsigned)__cvta_generic_to_shared(qHi);
    const unsigned qL = (unsigned)__cvta_generic_to_shared(qLo);
    const unsigned kH = (unsigned)__cvta_generic_to_shared(kHi);
    const unsigned kL = (unsigned)__cvta_generic_to_shared(kLo);

    // ---- phase 1: 256-wide k tiles, 16 warps = 2(m16) x 8(n32) ----
    const int wm1 = (warp & 1) << 4;
    const int wn1 = (warp >> 1) << 5;
    const int ntile1 = (q0 + 32 + 255) >> 8;

    // hoist Q fragments (constant across k tiles)
    unsigned qfh[4][4], qfl[4][4];
    {
        const int arow = wm1 + (lane & 15);
        #pragma unroll
        for (int ks = 0; ks < 4; ks++) {
            const int cb = (ks << 1) + lhi;
            ldsm4(qfh[ks], qH + sw_off(arow, cb));
            ldsm4(qfl[ks], qL + sw_off(arow, cb));
        }
    }

    for (int kt = 0; kt < ntile1; kt++) {
        const int k0 = kt << 8;
        const int nrow = (q0 + 32 - k0) < 256 ? (q0 + 32 - k0) : 256;
        const int n16  = nrow << 3;
        __syncthreads();
        {
            const uint4* gh = (const uint4*)(g_Khi + ((size_t)b << 16) + ((size_t)k0 << 6));
            const uint4* gl = (const uint4*)(g_Klo + ((size_t)b << 16) + ((size_t)k0 << 6));
            uint4* sh = (uint4*)kHi; uint4* sl = (uint4*)kLo;
            #pragma unroll
            for (int i = 0; i < 4; i++) {
                int f = tid + (i << 9);
                if (f < n16) { sh[f] = gh[f]; sl[f] = gl[f]; }
            }
        }
        // bias tile -> smem, coalesced
        #pragma unroll
        for (int i = 0; i < 2; i++) {
            int f = tid + (i << 9);
            int row = f >> 5, kcb = f & 31;
            *(uint4*)(sBias + row * 264 + (kcb << 3)) =
                *(const uint4*)(g_bias + ((size_t)b << 20) + ((size_t)(q0 + row) << 10) + k0 + (kcb << 3));
        }
        __syncthreads();

        const bool act1 = (k0 + wn1) <= (q0 + wm1 + 15);
        float c_[4][4] = {};
        if (act1) {
            #pragma unroll
            for (int ks = 0; ks < 4; ks++) {
                const int cb = (ks << 1) + lhi;
                unsigned b_hi[2][4], b_lo[2][4];
                #pragma unroll
                for (int h = 0; h < 2; h++) {
                    int brow = wn1 + (h << 4) + (lane & 15);
                    ldsm4(b_hi[h], kH + sw_off(brow, cb));
                    ldsm4(b_lo[h], kL + sw_off(brow, cb));
                }
                #pragma unroll
                for (int j = 0; j < 4; j++) {
                    const int h = j >> 1, o = j & 1;
                    unsigned bh[2] = {b_hi[h][o], b_hi[h][o + 2]};
                    unsigned bl[2] = {b_lo[h][o], b_lo[h][o + 2]};
                    mma_bf16(c_[j], qfh[ks], bh);
                    mma_bf16(c_[j], qfh[ks], bl);
                    mma_bf16(c_[j], qfl[ks], bh);
                }
            }
        }
        const int row0 = wm1 + (lane >> 2);
        const int coll = (lane & 3) << 1;
        if (act1) {
            #pragma unroll
            for (int j = 0; j < 4; j++) {
                int cloc = wn1 + (j << 3) + coll;
                int colk = k0 + cloc;
                {
                    int qr = q0 + row0;
                    float2 bs = bf2f(*(const unsigned*)&sBias[row0 * 264 + cloc]);
                    float s0 = (colk     <= qr) ? fmaf(c_[j][0], 0.125f, bs.x) : 0.f;
                    float s1 = (colk + 1 <= qr) ? fmaf(c_[j][1], 0.125f, bs.y) : 0.f;
                    *(float2*)&strip[row0 * STRIP + colk] = make_float2(s0, s1);
                }
                {
                    int qr = q0 + row0 + 8;
                    float2 bs = bf2f(*(const unsigned*)&sBias[(row0 + 8) * 264 + cloc]);
                    float s0 = (colk     <= qr) ? fmaf(c_[j][2], 0.125f, bs.x) : 0.f;
                    float s1 = (colk + 1 <= qr) ? fmaf(c_[j][3], 0.125f, bs.y) : 0.f;
                    *(float2*)&strip[(row0 + 8) * STRIP + colk] = make_float2(s0, s1);
                }
            }
        } else {
            #pragma unroll
            for (int j = 0; j < 4; j++) {
                int colk = k0 + wn1 + (j << 3) + coll;
                *(float2*)&strip[row0 * STRIP + colk]       = make_float2(0.f, 0.f);
                *(float2*)&strip[(row0 + 8) * STRIP + colk] = make_float2(0.f, 0.f);
            }
        }
    }
    __syncthreads();

    // ---- phase 2: softmax per row (exp into strip) ----
    {
        #pragma unroll
        for (int r = 0; r < 2; r++) {
            int row = (warp << 1) + r;
            int qr  = q0 + row;
            float m = -1e30f;
            for (int kk = lane; kk <= qr; kk += 32)
                m = fmaxf(m, strip[row * STRIP + kk]);
            #pragma unroll
            for (int o = 16; o; o >>= 1)
                m = fmaxf(m, __shfl_xor_sync(0xffffffffu, m, o));
            float ssum = 0.f;
            for (int kk = lane; kk <= qr; kk += 32) {
                float e = fast_exp(strip[row * STRIP + kk] - m);
                strip[row * STRIP + kk] = e;
                ssum += e;
            }
            #pragma unroll
            for (int o = 16; o; o >>= 1)
                ssum += __shfl_xor_sync(0xffffffffu, ssum, o);
            if (lane == 0) sInv[row] = 1.0f / ssum;
        }
    }
    __syncthreads();

    // ---- stage/convert: write attn AND convert strip -> split-P in place ----
    {
        float4 vreg[16];
        #pragma unroll
        for (int i = 0; i < 16; i++) {
            int f = tid + (i << 9);
            int row = f >> 8, kc = (f & 255) << 2;
            vreg[i] = *(const float4*)&strip[row * STRIP + kc];
        }
        __syncthreads();
        #pragma unroll
        for (int i = 0; i < 16; i++) {
            int f = tid + (i << 9);
            int row = f >> 8, kc = (f & 255) << 2;
            int qr  = q0 + row;
            float inv = sInv[row];
            float4 e = vreg[i];
            float4 o;
            o.x = (kc     <= qr) ? e.x * inv : 0.f;
            o.y = (kc + 1 <= qr) ? e.y * inv : 0.f;
            o.z = (kc + 2 <= qr) ? e.z * inv : 0.f;
            o.w = (kc + 3 <= qr) ? e.w * inv : 0.f;
            *(float4*)&attn[((size_t)b << 20) + ((size_t)qr << 10) + kc] = o;
            int t = kc >> 6;
            split_store(pHi + (t << 11), pLo + (t << 11), row, kc & 63, e);
        }
    }

    // ---- phase 4: out = P @ V.  128-wide k tiles, 16 warps = 2m x 2n x 4kg ----
    const int wm4 = (warp & 1) << 4;
    const int wn4 = ((warp >> 1) & 1) << 5;
    const int kg  = warp >> 2;
    const int ntile4 = (q0 + 32 + 127) >> 7;
    const unsigned pH = (unsigned)__cvta_generic_to_shared(pHi);
    const unsigned pL = (unsigned)__cvta_generic_to_shared(pLo);
    const unsigned vH = (unsigned)__cvta_generic_to_shared(vHi);
    const unsigned vL = (unsigned)__cvta_generic_to_shared(vLo);

    float c4[4][4] = {};

    for (int kt = 0; kt < ntile4; kt++) {
        const int k0 = kt << 7;
        const int nrow4 = (q0 + 32 - k0) < 128 ? (q0 + 32 - k0) : 128;
        const int n16v  = nrow4 << 3;
        __syncthreads();
        {
            const uint4* gh = (const uint4*)(g_Vhi + ((size_t)b << 16) + ((size_t)k0 << 6));
            const uint4* gl = (const uint4*)(g_Vlo + ((size_t)b << 16) + ((size_t)k0 << 6));
            uint4* sh = (uint4*)vHi; uint4* sl = (uint4*)vLo;
            #pragma unroll
            for (int i = 0; i < 2; i++) {
                int f = tid + (i << 9);
                if (f < n16v) { sh[f] = gh[f]; sl[f] = gl[f]; }
            }
        }
        __syncthreads();

        const bool act4 = (k0 + (kg << 5)) <= (q0 + 31);
        if (act4) {
            const int arow = wm4 + (lane & 15);
            #pragma unroll
            for (int ks = 0; ks < 2; ks++) {
                const int gk = k0 + (kg << 5) + (ks << 4);
                const int t  = gk >> 6;
                const int cbb = (gk & 63) >> 3;
                unsigned a_hi[4], a_lo[4];
                ldsm4(a_hi, pH + (t << 12) + sw_off(arow, cbb + lhi));
                ldsm4(a_lo, pL + (t << 12) + sw_off(arow, cbb + lhi));
                unsigned b_hi[2][4], b_lo[2][4];
                const int brow = (gk - k0) + (lane & 15);
                #pragma unroll
                for (int h = 0; h < 2; h++) {
                    int bcb = ((wn4 + (h << 4)) >> 3) + lhi;
                    ldsm4t(b_hi[h], vH + sw_off(brow, bcb));
                    ldsm4t(b_lo[h], vL + sw_off(brow, bcb));
                }
                #pragma unroll
                for (int j = 0; j < 4; j++) {
                    const int h = j >> 1, o = j & 1;
                    unsigned bh[2] = {b_hi[h][o << 1], b_hi[h][(o << 1) + 1]};
                    unsigned bl[2] = {b_lo[h][o << 1], b_lo[h][(o << 1) + 1]};
                    mma_bf16(c4[j], a_hi, bh);
                    mma_bf16(c4[j], a_hi, bl);
                    mma_bf16(c4[j], a_lo, bh);
                }
            }
        }
    }
    __syncthreads();

    const int row0 = wm4 + (lane >> 2);
    const int coll = (lane & 3) << 1;
    if (kg > 0) {
        #pragma unroll
        for (int j = 0; j < 4; j++) {
            int col = wn4 + (j << 3) + coll;
            *(float2*)&red[((kg - 1) << 11) + (row0 << 6) + col] =
                make_float2(c4[j][0], c4[j][1]);
            *(float2*)&red[((kg - 1) << 11) + ((row0 + 8) << 6) + col] =
                make_float2(c4[j][2], c4[j][3]);
        }
    }
    __syncthreads();
    if (kg == 0) {
        const float inv0 = sInv[row0];
        const float inv1 = sInv[row0 + 8];
        #pragma unroll
        for (int j = 0; j < 4; j++) {
            int col = wn4 + (j << 3) + coll;
            float2 s0 = make_float2(c4[j][0], c4[j][1]);
            float2 s1 = make_float2(c4[j][2], c4[j][3]);
            #pragma unroll
            for (int g = 0; g < 3; g++) {
                float2 p0 = *(const float2*)&red[(g << 11) + (row0 << 6) + col];
                float2 p1 = *(const float2*)&red[(g << 11) + ((row0 + 8) << 6) + col];
                s0.x += p0.x; s0.y += p0.y;
                s1.x += p1.x; s1.y += p1.y;
            }
            *(float2*)&out[((size_t)b << 16) + ((size_t)(q0 + row0) << 6) + col] =
                make_float2(s0.x * inv0, s0.y * inv0);
            *(float2*)&out[((size_t)b << 16) + ((size_t)(q0 + row0 + 8) << 6) + col] =
                make_float2(s1.x * inv1, s1.y * inv1);
        }
    }
}

// ---------------------------------------------------------------------------
// Kernel 3: out[b,q,d] += sum_k attn[b,q,k] * R_v[q,k,d]
// 512 threads, 16 warps = 4(m16) x 4(n16) — doubled concurrency.
// ---------------------------------------------------------------------------
__global__ void __launch_bounds__(512) k_rv(const float* __restrict__ attn,
                                            const float* __restrict__ Rv,
                                            float* __restrict__ out)
{
    const int q   = 1023 - blockIdx.x;
    const int tid = threadIdx.x;
    const int ntile = (q >> 6) + 1;

    __shared__ __align__(16) __nv_bfloat16 aHi[4096], aLo[4096], bHi[4096], bLo[4096];

    const int warp = tid >> 5, lane = tid & 31;
    const int wm = (warp & 3) << 4;
    const int wn = (warp >> 2) << 4;   // n16 per warp

    const unsigned aH = (unsigned)__cvta_generic_to_shared(aHi);
    const unsigned aL = (unsigned)__cvta_generic_to_shared(aLo);
    const unsigned bH = (unsigned)__cvta_generic_to_shared(bHi);
    const unsigned bL = (unsigned)__cvta_generic_to_shared(bLo);

    const int arow = wm + (lane & 15);
    const int lhi  = lane >> 4;

    float c_[2][4] = {};

    for (int kt = 0; kt < ntile; kt++) {
        const int k0 = kt << 6;
        __syncthreads();
        #pragma unroll
        for (int i = 0; i < 2; i++) {
            int f = tid + (i << 9); int r = f >> 4, c = (f & 15) << 2;
            float4 v = *(const float4*)&attn[((size_t)r << 20) + ((size_t)q << 10) + (size_t)(k0 + c)];
            split_store(aHi, aLo, r, c, v);
        }
        #pragma unroll
        for (int i = 0; i < 2; i++) {
            int f = tid + (i << 9); int r = f >> 4, c = (f & 15) << 2;
            float4 v = *(const float4*)&Rv[(((size_t)q << 10) + (size_t)(k0 + r)) * 64 + c];
            split_store(bHi, bLo, r, c, v);
        }
        __syncthreads();

        #pragma unroll
        for (int ks = 0; ks < 4; ks++) {
            const int cb = (ks << 1) + lhi;
            unsigned a_hi[4], a_lo[4];
            ldsm4(a_hi, aH + sw_off(arow, cb));
            ldsm4(a_lo, aL + sw_off(arow, cb));
            unsigned b_hi[4], b_lo[4];
            {
                int brow = (ks << 4) + (lane & 15);
                int bcb  = (wn >> 3) + lhi;
                ldsm4t(b_hi, bH + sw_off(brow, bcb));
                ldsm4t(b_lo, bL + sw_off(brow, bcb));
            }
            #pragma unroll
            for (int j = 0; j < 2; j++) {
                unsigned bh[2] = {b_hi[j << 1], b_hi[(j << 1) + 1]};
                unsigned bl[2] = {b_lo[j << 1], b_lo[(j << 1) + 1]};
                mma_bf16(c_[j], a_hi, bh);
                mma_bf16(c_[j], a_hi, bl);
                mma_bf16(c_[j], a_lo, bh);
            }
        }
    }

    const int row0 = wm + (lane >> 2);
    const int coll = (lane & 3) << 1;
    #pragma unroll
    for (int j = 0; j < 2; j++) {
        int col = wn + (j << 3) + coll;
        {
            float2* p = (float2*)&out[((size_t)row0 << 16) + ((size_t)q << 6) + col];
            float2 o = *p; o.x += c_[j][0]; o.y += c_[j][1]; *p = o;
        }
        {
            float2* p = (float2*)&out[((size_t)(row0 + 8) << 16) + ((size_t)q << 6) + col];
            float2 o = *p; o.x += c_[j][2]; o.y += c_[j][3]; *p = o;
        }
    }
}

// ---------------------------------------------------------------------------
extern "C" void kernel_launch(void* const* d_in, const int* in_sizes, int n_in,
                              void* d_out, int out_size)
{
    const float* Q  = (const float*)d_in[0];
    const float* K  = (const float*)d_in[1];
    const float* V  = (const float*)d_in[2];
    const float* Rk = (const float*)d_in[3];
    const float* Rv = (const float*)d_in[4];
    float* out  = (float*)d_out;
    float* attn = out + SZ_OUT;

    const int smem2 = 32 * STRIP * (int)sizeof(float)
                    + 36864 * (int)sizeof(__nv_bfloat16)
                    + 32 * 264 * (int)sizeof(__nv_bfloat16);
    cudaFuncSetAttribute(k_attn, cudaFuncAttributeMaxDynamicSharedMemorySize, smem2);

    k_prep<<<dim3(64, 8), 256>>>(K, V);
    k_bias<<<dim3(16, 1024), 256>>>(Q, Rk);
    k_attn<<<dim3(64, 32), 512, smem2>>>(Q, attn, out);
    k_rv<<<1024, 512>>>(attn, Rv, out);
}

// round 16
// speedup vs baseline: 1.1678x; 1.1678x over previous
#include <cuda_runtime.h>
#include <cuda_bf16.h>

#define SZ_OUT (64ull * 1024ull * 64ull)
#define STRIP 1028

// bf16 bias scratch: [b][q][k]
__device__ __align__(16) __nv_bfloat16 g_bias[1ull << 26];
// pre-split K/V in swizzled tile layout: idx = b<<16 | row<<6 | swizzled-col
__device__ __align__(16) __nv_bfloat16 g_Khi[1ull << 22], g_Klo[1ull << 22];
__device__ __align__(16) __nv_bfloat16 g_Vhi[1ull << 22], g_Vlo[1ull << 22];

// ===========================================================================
// bf16 split-GEMM helpers (mma.sync m16n8k16, 3-MMA fp32 emulation)
// ===========================================================================
__device__ __forceinline__ unsigned pk_bf2(float a, float b) {
    __nv_bfloat162 t = __floats2bfloat162_rn(a, b);
    return *reinterpret_cast<unsigned*>(&t);
}
__device__ __forceinline__ float2 bf2f(unsigned u) {
    __nv_bfloat162 h = *reinterpret_cast<__nv_bfloat162*>(&u);
    return __bfloat1622float2(h);
}

__device__ __forceinline__ void split_store(__nv_bfloat16* hi, __nv_bfloat16* lo,
                                            int r, int c, float4 v)
{
    int cb  = c >> 3;
    int off = (r << 6) + ((cb ^ (r & 7)) << 3) + (c & 7);
    float hx = __bfloat162float(__float2bfloat16(v.x));
    float hy = __bfloat162float(__float2bfloat16(v.y));
    float hz = __bfloat162float(__float2bfloat16(v.z));
    float hw = __bfloat162float(__float2bfloat16(v.w));
    *(uint2*)(hi + off) = make_uint2(pk_bf2(hx, hy), pk_bf2(hz, hw));
    *(uint2*)(lo + off) = make_uint2(pk_bf2(v.x - hx, v.y - hy),
                                     pk_bf2(v.z - hz, v.w - hw));
}

__device__ __forceinline__ void ldsm4(unsigned* r, unsigned addr) {
    asm volatile("ldmatrix.sync.aligned.m8n8.x4.shared.b16 {%0,%1,%2,%3}, [%4];"
                 : "=r"(r[0]), "=r"(r[1]), "=r"(r[2]), "=r"(r[3]) : "r"(addr));
}
__device__ __forceinline__ void ldsm4t(unsigned* r, unsigned addr) {
    asm volatile("ldmatrix.sync.aligned.m8n8.x4.trans.shared.b16 {%0,%1,%2,%3}, [%4];"
                 : "=r"(r[0]), "=r"(r[1]), "=r"(r[2]), "=r"(r[3]) : "r"(addr));
}
__device__ __forceinline__ void mma_bf16(float* c, const unsigned* a, const unsigned* b) {
    asm volatile("mma.sync.aligned.m16n8k16.row.col.f32.bf16.bf16.f32 "
                 "{%0,%1,%2,%3}, {%4,%5,%6,%7}, {%8,%9}, {%0,%1,%2,%3};"
                 : "+f"(c[0]), "+f"(c[1]), "+f"(c[2]), "+f"(c[3])
                 : "r"(a[0]), "r"(a[1]), "r"(a[2]), "r"(a[3]), "r"(b[0]), "r"(b[1]));
}

__device__ __forceinline__ unsigned sw_off(int r, int cb) {
    return (unsigned)((r << 7) + (((cb ^ (r & 7))) << 4));
}

__device__ __forceinline__ void cp16(unsigned saddr, const void* g) {
    asm volatile("cp.async.cg.shared.global [%0], [%1], 16;" :: "r"(saddr), "l"(g));
}
#define CP_COMMIT() asm volatile("cp.async.commit_group;" ::: "memory")
#define CP_WAIT0()  asm volatile("cp.async.wait_group 0;" ::: "memory")
#define CP_WAIT1()  asm volatile("cp.async.wait_group 1;" ::: "memory")

// FFMA-pipe exp for t <= 0
__device__ __forceinline__ float fast_exp(float t) {
    float y = t * 1.4426950408889634f;
    int   n = __float2int_rn(y);
    float f = y - (float)n;
    float p = 1.3333558146428443e-3f;
    p = fmaf(p, f, 9.6181291076284772e-3f);
    p = fmaf(p, f, 5.5504108664821580e-2f);
    p = fmaf(p, f, 2.4022650695910071e-1f);
    p = fmaf(p, f, 6.9314718055994531e-1f);
    p = fmaf(p, f, 1.0f);
    int e = n + 127;
    e = e < 0 ? 0 : e;
    return p * __int_as_float(e << 23);
}

// ---------------------------------------------------------------------------
// Kernel 0: pre-split K and V to swizzled bf16 hi/lo. Grid (64 b, 8 rowblocks).
// ---------------------------------------------------------------------------
__global__ void __launch_bounds__(256) k_prep(const float* __restrict__ K,
                                              const float* __restrict__ V)
{
    const int b  = blockIdx.x;
    const int r0 = blockIdx.y << 7;
    const int tid = threadIdx.x;
    __nv_bfloat16* kh = g_Khi + ((size_t)b << 16);
    __nv_bfloat16* kl = g_Klo + ((size_t)b << 16);
    __nv_bfloat16* vh = g_Vhi + ((size_t)b << 16);
    __nv_bfloat16* vl = g_Vlo + ((size_t)b << 16);
    #pragma unroll
    for (int i = 0; i < 8; i++) {
        int f = tid + (i << 8);
        int r = r0 + (f >> 4), c = (f & 15) << 2;
        float4 kv = *(const float4*)&K[((size_t)b << 16) + ((size_t)r << 6) + c];
        float4 vv = *(const float4*)&V[((size_t)b << 16) + ((size_t)r << 6) + c];
        split_store(kh, kl, r, c, kv);
        split_store(vh, vl, r, c, vv);
    }
}

// ---------------------------------------------------------------------------
// Kernel 1: g_bias[b,q,k] = bf16( 0.125 * sum_d Q[b,q,d] * R_k[q,k,d] )
// ---------------------------------------------------------------------------
__global__ void __launch_bounds__(256) k_bias(const float* __restrict__ Q,
                                              const float* __restrict__ Rk)
{
    const int q  = blockIdx.y;
    const int k0 = blockIdx.x << 6;
    if (k0 > q) return;

    __shared__ __align__(16) __nv_bfloat16 aHi[4096], aLo[4096], bHi[4096], bLo[4096];
    const int tid = threadIdx.x;

    #pragma unroll
    for (int i = 0; i < 4; i++) {
        int f = tid + (i << 8); int r = f >> 4, c = (f & 15) << 2;
        float4 v = *(const float4*)&Q[((size_t)r << 16) + ((size_t)q << 6) + c];
        split_store(aHi, aLo, r, c, v);
    }
    #pragma unroll
    for (int i = 0; i < 4; i++) {
        int f = tid + (i << 8); int r = f >> 4, c = (f & 15) << 2;
        float4 v = *(const float4*)&Rk[(((size_t)q << 10) + (size_t)(k0 + r)) * 64 + c];
        split_store(bHi, bLo, r, c, v);
    }
    __syncthreads();

    const int warp = tid >> 5, lane = tid & 31;
    const int wm = (warp & 3) << 4;
    const int wn = (warp >> 2) << 5;

    const unsigned aH = (unsigned)__cvta_generic_to_shared(aHi);
    const unsigned aL = (unsigned)__cvta_generic_to_shared(aLo);
    const unsigned bH = (unsigned)__cvta_generic_to_shared(bHi);
    const unsigned bL = (unsigned)__cvta_generic_to_shared(bLo);

    const int arow = wm + (lane & 15);
    const int lhi  = lane >> 4;

    float c_[4][4] = {};

    #pragma unroll
    for (int ks = 0; ks < 4; ks++) {
        const int cb = (ks << 1) + lhi;
        unsigned a_hi[4], a_lo[4];
        ldsm4(a_hi, aH + sw_off(arow, cb));
        ldsm4(a_lo, aL + sw_off(arow, cb));
        unsigned b_hi[2][4], b_lo[2][4];
        #pragma unroll
        for (int h = 0; h < 2; h++) {
            int brow = wn + (h << 4) + (lane & 15);
            ldsm4(b_hi[h], bH + sw_off(brow, cb));
            ldsm4(b_lo[h], bL + sw_off(brow, cb));
        }
        #pragma unroll
        for (int j = 0; j < 4; j++) {
            const int h = j >> 1, o = j & 1;
            unsigned bh[2] = {b_hi[h][o], b_hi[h][o + 2]};
            unsigned bl[2] = {b_lo[h][o], b_lo[h][o + 2]};
            mma_bf16(c_[j], a_hi, bh);
            mma_bf16(c_[j], a_hi, bl);
            mma_bf16(c_[j], a_lo, bh);
        }
    }

    const int row0 = wm + (lane >> 2);
    const int coll = (lane & 3) << 1;
    #pragma unroll
    for (int j = 0; j < 4; j++) {
        int col = k0 + wn + (j << 3) + coll;
        *(unsigned*)&g_bias[((size_t)row0 << 20) + ((size_t)q << 10) + col] =
            pk_bf2(c_[j][0] * 0.125f, c_[j][1] * 0.125f);
        *(unsigned*)&g_bias[((size_t)(row0 + 8) << 20) + ((size_t)q << 10) + col] =
            pk_bf2(c_[j][2] * 0.125f, c_[j][3] * 0.125f);
    }
}

// ---------------------------------------------------------------------------
// Kernel 2: per (b, 32-row q strip). 512 threads, ~222 KB smem.
// cp.async double-buffered tiles in phase1 (K+bias) and phase4 (V).
// ---------------------------------------------------------------------------
__global__ void __launch_bounds__(512) k_attn(const float* __restrict__ Q,
                                              float* attn,
                                              float* __restrict__ out)
{
    extern __shared__ float sm[];
    float* strip = sm;                                      // [32][1028] fp32
    __nv_bfloat16* pHi = (__nv_bfloat16*)sm;                // after convert
    __nv_bfloat16* pLo = (__nv_bfloat16*)sm + 32768;
    __nv_bfloat16* bufs = (__nv_bfloat16*)(sm + 32 * STRIP);
    __nv_bfloat16* qHi = bufs;                              // 2048
    __nv_bfloat16* qLo = bufs + 2048;                       // 2048
    // phase1 K double buffers: kHi_p = bufs+4096+p*16384, kLo_p = +8192
    // phase4 V double buffers: vHi_p = bufs+p*16384, vLo_p = +8192
    float* red = (float*)(bufs + 32768);                    // 2048 floats
    __nv_bfloat16* sBias = bufs + 36864;                    // 2 x [32][136]
    __shared__ float sInv[32];

    const int b   = blockIdx.x;
    const int q0  = (gridDim.y - 1 - blockIdx.y) << 5;
    const int tid = threadIdx.x;
    const int warp = tid >> 5, lane = tid & 31, lhi = lane >> 4;

    const unsigned bufsA = (unsigned)__cvta_generic_to_shared(bufs);
    const unsigned sBiasA = (unsigned)__cvta_generic_to_shared(sBias);

    {
        int r = tid >> 4, c = (tid & 15) << 2;
        float4 v = *(const float4*)&Q[((size_t)b << 16) + ((size_t)(q0 + r) << 6) + c];
        split_store(qHi, qLo, r, c, v);
    }
    __syncthreads();

    const unsigned qH = (unsigned)__cvta_generic_to_shared(qHi);
    const unsigned qL = (unsigned)__cvta_generic_to_shared(qLo);

    // ---- phase 1: 128-wide k tiles, 16 warps = 2(m16) x 8(n16) ----
    const int wm1 = (warp & 1) << 4;
    const int wn1 = (warp >> 1) << 4;
    const int ntile1 = (q0 + 32 + 127) >> 7;

    // hoist Q fragments
    unsigned qfh[4][4], qfl[4][4];
    {
        const int arow = wm1 + (lane & 15);
        #pragma unroll
        for (int ks = 0; ks < 4; ks++) {
            const int cb = (ks << 1) + lhi;
            ldsm4(qfh[ks], qH + sw_off(arow, cb));
            ldsm4(qfl[ks], qL + sw_off(arow, cb));
        }
    }

    // async K+bias tile loader
    auto load_k = [&](int kt) {
        const int p  = kt & 1;
        const int k0 = kt << 7;
        int nrow = q0 + 32 - k0; if (nrow > 128) nrow = 128;
        const int n16 = nrow << 3;
        const uint4* gh = (const uint4*)(g_Khi + ((size_t)b << 16) + ((size_t)k0 << 6));
        const uint4* gl = (const uint4*)(g_Klo + ((size_t)b << 16) + ((size_t)k0 << 6));
        const unsigned sh = bufsA + 8192 + (p << 15);        // kHi_p bytes
        const unsigned sl = sh + 16384;                      // kLo_p
        #pragma unroll
        for (int i = 0; i < 2; i++) {
            int f = tid + (i << 9);
            if (f < n16) {
                cp16(sh + (f << 4), gh + f);
                cp16(sl + (f << 4), gl + f);
            }
        }
        {
            int row = tid >> 4, cb = tid & 15;
            cp16(sBiasA + ((p * 4352 + row * 136 + (cb << 3)) << 1),
                 g_bias + ((size_t)b << 20) + ((size_t)(q0 + row) << 10) + k0 + (cb << 3));
        }
        CP_COMMIT();
    };

    load_k(0);
    for (int kt = 0; kt < ntile1; kt++) {
        const int p  = kt & 1;
        const int k0 = kt << 7;
        const bool more = (kt + 1 < ntile1);
        if (more) load_k(kt + 1);
        if (more) { CP_WAIT1(); } else { CP_WAIT0(); }
        __syncthreads();

        const unsigned kHp = bufsA + 8192 + (p << 15);
        const unsigned kLp = kHp + 16384;
        const bool act1 = (k0 + wn1) <= (q0 + wm1 + 15);
        float c_[2][4] = {};
        if (act1) {
            const int brow = wn1 + (lane & 15);
            #pragma unroll
            for (int ks = 0; ks < 4; ks++) {
                const int cb = (ks << 1) + lhi;
                unsigned b_hi[4], b_lo[4];
                ldsm4(b_hi, kHp + sw_off(brow, cb));
                ldsm4(b_lo, kLp + sw_off(brow, cb));
                #pragma unroll
                for (int j = 0; j < 2; j++) {
                    unsigned bh[2] = {b_hi[j], b_hi[j + 2]};
                    unsigned bl[2] = {b_lo[j], b_lo[j + 2]};
                    mma_bf16(c_[j], qfh[ks], bh);
                    mma_bf16(c_[j], qfh[ks], bl);
                    mma_bf16(c_[j], qfl[ks], bh);
                }
            }
        }
        const int row0 = wm1 + (lane >> 2);
        const int coll = (lane & 3) << 1;
        const int bb = p * 4352;
        if (act1) {
            #pragma unroll
            for (int j = 0; j < 2; j++) {
                int cloc = wn1 + (j << 3) + coll;
                int colk = k0 + cloc;
                {
                    int qr = q0 + row0;
                    float2 bs = bf2f(*(const unsigned*)&sBias[bb + row0 * 136 + cloc]);
                    float s0 = (colk     <= qr) ? fmaf(c_[j][0], 0.125f, bs.x) : 0.f;
                    float s1 = (colk + 1 <= qr) ? fmaf(c_[j][1], 0.125f, bs.y) : 0.f;
                    *(float2*)&strip[row0 * STRIP + colk] = make_float2(s0, s1);
                }
                {
                    int qr = q0 + row0 + 8;
                    float2 bs = bf2f(*(const unsigned*)&sBias[bb + (row0 + 8) * 136 + cloc]);
                    float s0 = (colk     <= qr) ? fmaf(c_[j][2], 0.125f, bs.x) : 0.f;
                    float s1 = (colk + 1 <= qr) ? fmaf(c_[j][3], 0.125f, bs.y) : 0.f;
                    *(float2*)&strip[(row0 + 8) * STRIP + colk] = make_float2(s0, s1);
                }
            }
        } else {
            #pragma unroll
            for (int j = 0; j < 2; j++) {
                int colk = k0 + wn1 + (j << 3) + coll;
                *(float2*)&strip[row0 * STRIP + colk]       = make_float2(0.f, 0.f);
                *(float2*)&strip[(row0 + 8) * STRIP + colk] = make_float2(0.f, 0.f);
            }
        }
        __syncthreads();
    }

    // ---- phase 2: softmax per row (exp into strip) ----
    {
        #pragma unroll
        for (int r = 0; r < 2; r++) {
            int row = (warp << 1) + r;
            int qr  = q0 + row;
            float m = -1e30f;
            for (int kk = lane; kk <= qr; kk += 32)
                m = fmaxf(m, strip[row * STRIP + kk]);
            #pragma unroll
            for (int o = 16; o; o >>= 1)
                m = fmaxf(m, __shfl_xor_sync(0xffffffffu, m, o));
            float ssum = 0.f;
            for (int kk = lane; kk <= qr; kk += 32) {
                float e = fast_exp(strip[row * STRIP + kk] - m);
                strip[row * STRIP + kk] = e;
                ssum += e;
            }
            #pragma unroll
            for (int o = 16; o; o >>= 1)
                ssum += __shfl_xor_sync(0xffffffffu, ssum, o);
            if (lane == 0) sInv[row] = 1.0f / ssum;
        }
    }
    __syncthreads();

    // ---- stage/convert: write attn AND convert strip -> split-P in place ----
    {
        float4 vreg[16];
        #pragma unroll
        for (int i = 0; i < 16; i++) {
            int f = tid + (i << 9);
            int row = f >> 8, kc = (f & 255) << 2;
            vreg[i] = *(const float4*)&strip[row * STRIP + kc];
        }
        __syncthreads();
        #pragma unroll
        for (int i = 0; i < 16; i++) {
            int f = tid + (i << 9);
            int row = f >> 8, kc = (f & 255) << 2;
            int qr  = q0 + row;
            float inv = sInv[row];
            float4 e = vreg[i];
            float4 o;
            o.x = (kc     <= qr) ? e.x * inv : 0.f;
            o.y = (kc + 1 <= qr) ? e.y * inv : 0.f;
            o.z = (kc + 2 <= qr) ? e.z * inv : 0.f;
            o.w = (kc + 3 <= qr) ? e.w * inv : 0.f;
            *(float4*)&attn[((size_t)b << 20) + ((size_t)qr << 10) + kc] = o;
            int t = kc >> 6;
            split_store(pHi + (t << 11), pLo + (t << 11), row, kc & 63, e);
        }
    }

    // ---- phase 4: out = P @ V. 128-wide tiles, 16 warps = 2m x 4n(16) x 2kg ----
    const int wm4 = (warp & 1) << 4;
    const int wn4 = ((warp >> 1) & 3) << 4;
    const int kg  = warp >> 3;
    const int ntile4 = (q0 + 32 + 127) >> 7;
    const unsigned pH = (unsigned)__cvta_generic_to_shared(pHi);
    const unsigned pL = (unsigned)__cvta_generic_to_shared(pLo);

    auto load_v = [&](int kt) {
        const int p  = kt & 1;
        const int k0 = kt << 7;
        int nrow = q0 + 32 - k0; if (nrow > 128) nrow = 128;
        const int n16 = nrow << 3;
        const uint4* gh = (const uint4*)(g_Vhi + ((size_t)b << 16) + ((size_t)k0 << 6));
        const uint4* gl = (const uint4*)(g_Vlo + ((size_t)b << 16) + ((size_t)k0 << 6));
        const unsigned sh = bufsA + (p << 15);
        const unsigned sl = sh + 16384;
        #pragma unroll
        for (int i = 0; i < 2; i++) {
            int f = tid + (i << 9);
            if (f < n16) {
                cp16(sh + (f << 4), gh + f);
                cp16(sl + (f << 4), gl + f);
            }
        }
        CP_COMMIT();
    };

    float c4[2][4] = {};

    load_v(0);
    for (int kt = 0; kt < ntile4; kt++) {
        const int p  = kt & 1;
        const int k0 = kt << 7;
        const bool more = (kt + 1 < ntile4);
        if (more) load_v(kt + 1);
        if (more) { CP_WAIT1(); } else { CP_WAIT0(); }
        __syncthreads();

        const unsigned vHp = bufsA + (p << 15);
        const unsigned vLp = vHp + 16384;
        const bool act4 = (k0 + (kg << 6)) <= (q0 + 31);
        if (act4) {
            const int arow = wm4 + (lane & 15);
            #pragma unroll
            for (int ks = 0; ks < 4; ks++) {
                const int gk = k0 + (kg << 6) + (ks << 4);
                const int t  = gk >> 6;
                const int cbb = (gk & 63) >> 3;
                unsigned a_hi[4], a_lo[4];
                ldsm4(a_hi, pH + (t << 12) + sw_off(arow, cbb + lhi));
                ldsm4(a_lo, pL + (t << 12) + sw_off(arow, cbb + lhi));
                unsigned b_hi[4], b_lo[4];
                const int brow = (gk - k0) + (lane & 15);
                const int bcb = (wn4 >> 3) + lhi;
                ldsm4t(b_hi, vHp + sw_off(brow, bcb));
                ldsm4t(b_lo, vLp + sw_off(brow, bcb));
                #pragma unroll
                for (int j = 0; j < 2; j++) {
                    unsigned bh[2] = {b_hi[j << 1], b_hi[(j << 1) + 1]};
                    unsigned bl[2] = {b_lo[j << 1], b_lo[(j << 1) + 1]};
                    mma_bf16(c4[j], a_hi, bh);
                    mma_bf16(c4[j], a_hi, bl);
                    mma_bf16(c4[j], a_lo, bh);
                }
            }
        }
        __syncthreads();
    }

    const int row0 = wm4 + (lane >> 2);
    const int coll = (lane & 3) << 1;
    if (kg == 1) {
        #pragma unroll
        for (int j = 0; j < 2; j++) {
            int col = wn4 + (j << 3) + coll;
            *(float2*)&red[(row0 << 6) + col] = make_float2(c4[j][0], c4[j][1]);
            *(float2*)&red[((row0 + 8) << 6) + col] = make_float2(c4[j][2], c4[j][3]);
        }
    }
    __syncthreads();
    if (kg == 0) {
        const float inv0 = sInv[row0];
        const float inv1 = sInv[row0 + 8];
        #pragma unroll
        for (int j = 0; j < 2; j++) {
            int col = wn4 + (j << 3) + coll;
            float2 p0 = *(const float2*)&red[(row0 << 6) + col];
            float2 p1 = *(const float2*)&red[((row0 + 8) << 6) + col];
            *(float2*)&out[((size_t)b << 16) + ((size_t)(q0 + row0) << 6) + col] =
                make_float2((c4[j][0] + p0.x) * inv0, (c4[j][1] + p0.y) * inv0);
            *(float2*)&out[((size_t)b << 16) + ((size_t)(q0 + row0 + 8) << 6) + col] =
                make_float2((c4[j][2] + p1.x) * inv1, (c4[j][3] + p1.y) * inv1);
        }
    }
}

// ---------------------------------------------------------------------------
// Kernel 3: out[b,q,d] += sum_k attn[b,q,k] * R_v[q,k,d]  (R13 version, 256 thr)
// ---------------------------------------------------------------------------
__global__ void __launch_bounds__(256) k_rv(const float* __restrict__ attn,
                                            const float* __restrict__ Rv,
                                            float* __restrict__ out)
{
    const int q   = 1023 - blockIdx.x;
    const int tid = threadIdx.x;
    const int ntile = (q >> 6) + 1;

    __shared__ __align__(16) __nv_bfloat16 aHi[4096], aLo[4096], bHi[4096], bLo[4096];

    const int warp = tid >> 5, lane = tid & 31;
    const int wm = (warp & 3) << 4;
    const int wn = (warp >> 2) << 5;

    const unsigned aH = (unsigned)__cvta_generic_to_shared(aHi);
    const unsigned aL = (unsigned)__cvta_generic_to_shared(aLo);
    const unsigned bH = (unsigned)__cvta_generic_to_shared(bHi);
    const unsigned bL = (unsigned)__cvta_generic_to_shared(bLo);

    const int arow = wm + (lane & 15);
    const int lhi  = lane >> 4;

    float c_[4][4] = {};

    for (int kt = 0; kt < ntile; kt++) {
        const int k0 = kt << 6;
        __syncthreads();
        #pragma unroll
        for (int i = 0; i < 4; i++) {
            int f = tid + (i << 8); int r = f >> 4, c = (f & 15) << 2;
            float4 v = *(const float4*)&attn[((size_t)r << 20) + ((size_t)q << 10) + (size_t)(k0 + c)];
            split_store(aHi, aLo, r, c, v);
        }
        #pragma unroll
        for (int i = 0; i < 4; i++) {
            int f = tid + (i << 8); int r = f >> 4, c = (f & 15) << 2;
            float4 v = *(const float4*)&Rv[(((size_t)q << 10) + (size_t)(k0 + r)) * 64 + c];
            split_store(bHi, bLo, r, c, v);
        }
        __syncthreads();

        #pragma unroll
        for (int ks = 0; ks < 4; ks++) {
            const int cb = (ks << 1) + lhi;
            unsigned a_hi[4], a_lo[4];
            ldsm4(a_hi, aH + sw_off(arow, cb));
            ldsm4(a_lo, aL + sw_off(arow, cb));
            unsigned b_hi[2][4], b_lo[2][4];
            #pragma unroll
            for (int h = 0; h < 2; h++) {
                int brow = (ks << 4) + (lane & 15);
                int bcb  = ((wn + (h << 4)) >> 3) + lhi;
                ldsm4t(b_hi[h], bH + sw_off(brow, bcb));
                ldsm4t(b_lo[h], bL + sw_off(brow, bcb));
            }
            #pragma unroll
            for (int j = 0; j < 4; j++) {
                const int h = j >> 1, o = j & 1;
                unsigned bh[2] = {b_hi[h][o << 1], b_hi[h][(o << 1) + 1]};
                unsigned bl[2] = {b_lo[h][o << 1], b_lo[h][(o << 1) + 1]};
                mma_bf16(c_[j], a_hi, bh);
                mma_bf16(c_[j], a_hi, bl);
                mma_bf16(c_[j], a_lo, bh);
            }
        }
    }

    const int row0 = wm + (lane >> 2);
    const int coll = (lane & 3) << 1;
    #pragma unroll
    for (int j = 0; j < 4; j++) {
        int col = wn + (j << 3) + coll;
        {
            float2* p = (float2*)&out[((size_t)row0 << 16) + ((size_t)q << 6) + col];
            float2 o = *p; o.x += c_[j][0]; o.y += c_[j][1]; *p = o;
        }
        {
            float2* p = (float2*)&out[((size_t)(row0 + 8) << 16) + ((size_t)q << 6) + col];
            float2 o = *p; o.x += c_[j][2]; o.y += c_[j][3]; *p = o;
        }
    }
}

// ---------------------------------------------------------------------------
extern "C" void kernel_launch(void* const* d_in, const int* in_sizes, int n_in,
                              void* d_out, int out_size)
{
    const float* Q  = (const float*)d_in[0];
    const float* K  = (const float*)d_in[1];
    const float* V  = (const float*)d_in[2];
    const float* Rk = (const float*)d_in[3];
    const float* Rv = (const float*)d_in[4];
    float* out  = (float*)d_out;
    float* attn = out + SZ_OUT;

    // strip 131584 + bufs 73728 + sBias 17408 = 222720 bytes
    const int smem2 = 32 * STRIP * (int)sizeof(float)
                    + 36864 * (int)sizeof(__nv_bfloat16)
                    + 8704 * (int)sizeof(__nv_bfloat16);
    cudaFuncSetAttribute(k_attn, cudaFuncAttributeMaxDynamicSharedMemorySize, smem2);

    k_prep<<<dim3(64, 8), 256>>>(K, V);
    k_bias<<<dim3(16, 1024), 256>>>(Q, Rk);
    k_attn<<<dim3(64, 32), 512, smem2>>>(Q, attn, out);
    k_rv<<<1024, 256>>>(attn, Rv, out);
}

// round 17
// speedup vs baseline: 1.2118x; 1.0377x over previous
#include <cuda_runtime.h>
#include <cuda_bf16.h>

#define SZ_OUT (64ull * 1024ull * 64ull)
#define STRIP 1028

// bf16 bias scratch: [b][q][k]
__device__ __align__(16) __nv_bfloat16 g_bias[1ull << 26];
// pre-split K/V in swizzled tile layout: idx = b<<16 | row<<6 | swizzled-col
__device__ __align__(16) __nv_bfloat16 g_Khi[1ull << 22], g_Klo[1ull << 22];
__device__ __align__(16) __nv_bfloat16 g_Vhi[1ull << 22], g_Vlo[1ull << 22];

// ===========================================================================
// bf16 split-GEMM helpers (mma.sync m16n8k16, 3-MMA fp32 emulation)
// ===========================================================================
__device__ __forceinline__ unsigned pk_bf2(float a, float b) {
    __nv_bfloat162 t = __floats2bfloat162_rn(a, b);
    return *reinterpret_cast<unsigned*>(&t);
}
__device__ __forceinline__ float2 bf2f(unsigned u) {
    __nv_bfloat162 h = *reinterpret_cast<__nv_bfloat162*>(&u);
    return __bfloat1622float2(h);
}

__device__ __forceinline__ void split_store(__nv_bfloat16* hi, __nv_bfloat16* lo,
                                            int r, int c, float4 v)
{
    int cb  = c >> 3;
    int off = (r << 6) + ((cb ^ (r & 7)) << 3) + (c & 7);
    float hx = __bfloat162float(__float2bfloat16(v.x));
    float hy = __bfloat162float(__float2bfloat16(v.y));
    float hz = __bfloat162float(__float2bfloat16(v.z));
    float hw = __bfloat162float(__float2bfloat16(v.w));
    *(uint2*)(hi + off) = make_uint2(pk_bf2(hx, hy), pk_bf2(hz, hw));
    *(uint2*)(lo + off) = make_uint2(pk_bf2(v.x - hx, v.y - hy),
                                     pk_bf2(v.z - hz, v.w - hw));
}

__device__ __forceinline__ void ldsm4(unsigned* r, unsigned addr) {
    asm volatile("ldmatrix.sync.aligned.m8n8.x4.shared.b16 {%0,%1,%2,%3}, [%4];"
                 : "=r"(r[0]), "=r"(r[1]), "=r"(r[2]), "=r"(r[3]) : "r"(addr));
}
__device__ __forceinline__ void ldsm4t(unsigned* r, unsigned addr) {
    asm volatile("ldmatrix.sync.aligned.m8n8.x4.trans.shared.b16 {%0,%1,%2,%3}, [%4];"
                 : "=r"(r[0]), "=r"(r[1]), "=r"(r[2]), "=r"(r[3]) : "r"(addr));
}
__device__ __forceinline__ void mma_bf16(float* c, const unsigned* a, const unsigned* b) {
    asm volatile("mma.sync.aligned.m16n8k16.row.col.f32.bf16.bf16.f32 "
                 "{%0,%1,%2,%3}, {%4,%5,%6,%7}, {%8,%9}, {%0,%1,%2,%3};"
                 : "+f"(c[0]), "+f"(c[1]), "+f"(c[2]), "+f"(c[3])
                 : "r"(a[0]), "r"(a[1]), "r"(a[2]), "r"(a[3]), "r"(b[0]), "r"(b[1]));
}

__device__ __forceinline__ unsigned sw_off(int r, int cb) {
    return (unsigned)((r << 7) + (((cb ^ (r & 7))) << 4));
}

__device__ __forceinline__ void cp16(unsigned saddr, const void* g) {
    asm volatile("cp.async.cg.shared.global [%0], [%1], 16;" :: "r"(saddr), "l"(g));
}
#define CP_COMMIT() asm volatile("cp.async.commit_group;" ::: "memory")
#define CP_WAIT0()  asm volatile("cp.async.wait_group 0;" ::: "memory")
#define CP_WAIT1()  asm volatile("cp.async.wait_group 1;" ::: "memory")

// FFMA-pipe exp for t <= 0
__device__ __forceinline__ float fast_exp(float t) {
    float y = t * 1.4426950408889634f;
    int   n = __float2int_rn(y);
    float f = y - (float)n;
    float p = 1.3333558146428443e-3f;
    p = fmaf(p, f, 9.6181291076284772e-3f);
    p = fmaf(p, f, 5.5504108664821580e-2f);
    p = fmaf(p, f, 2.4022650695910071e-1f);
    p = fmaf(p, f, 6.9314718055994531e-1f);
    p = fmaf(p, f, 1.0f);
    int e = n + 127;
    e = e < 0 ? 0 : e;
    return p * __int_as_float(e << 23);
}

// ---------------------------------------------------------------------------
// Kernel 0: pre-split K and V to swizzled bf16 hi/lo. Grid (64 b, 8 rowblocks).
// ---------------------------------------------------------------------------
__global__ void __launch_bounds__(256) k_prep(const float* __restrict__ K,
                                              const float* __restrict__ V)
{
    const int b  = blockIdx.x;
    const int r0 = blockIdx.y << 7;
    const int tid = threadIdx.x;
    __nv_bfloat16* kh = g_Khi + ((size_t)b << 16);
    __nv_bfloat16* kl = g_Klo + ((size_t)b << 16);
    __nv_bfloat16* vh = g_Vhi + ((size_t)b << 16);
    __nv_bfloat16* vl = g_Vlo + ((size_t)b << 16);
    #pragma unroll
    for (int i = 0; i < 8; i++) {
        int f = tid + (i << 8);
        int r = r0 + (f >> 4), c = (f & 15) << 2;
        float4 kv = *(const float4*)&K[((size_t)b << 16) + ((size_t)r << 6) + c];
        float4 vv = *(const float4*)&V[((size_t)b << 16) + ((size_t)r << 6) + c];
        split_store(kh, kl, r, c, kv);
        split_store(vh, vl, r, c, vv);
    }
}

// ---------------------------------------------------------------------------
// Kernel 1: g_bias[b,q,k] = bf16( 0.125 * sum_d Q[b,q,d] * R_k[q,k,d] )
// ---------------------------------------------------------------------------
__global__ void __launch_bounds__(256) k_bias(const float* __restrict__ Q,
                                              const float* __restrict__ Rk)
{
    const int q  = blockIdx.y;
    const int k0 = blockIdx.x << 6;
    if (k0 > q) return;

    __shared__ __align__(16) __nv_bfloat16 aHi[4096], aLo[4096], bHi[4096], bLo[4096];
    const int tid = threadIdx.x;

    #pragma unroll
    for (int i = 0; i < 4; i++) {
        int f = tid + (i << 8); int r = f >> 4, c = (f & 15) << 2;
        float4 v = *(const float4*)&Q[((size_t)r << 16) + ((size_t)q << 6) + c];
        split_store(aHi, aLo, r, c, v);
    }
    #pragma unroll
    for (int i = 0; i < 4; i++) {
        int f = tid + (i << 8); int r = f >> 4, c = (f & 15) << 2;
        float4 v = *(const float4*)&Rk[(((size_t)q << 10) + (size_t)(k0 + r)) * 64 + c];
        split_store(bHi, bLo, r, c, v);
    }
    __syncthreads();

    const int warp = tid >> 5, lane = tid & 31;
    const int wm = (warp & 3) << 4;
    const int wn = (warp >> 2) << 5;

    const unsigned aH = (unsigned)__cvta_generic_to_shared(aHi);
    const unsigned aL = (unsigned)__cvta_generic_to_shared(aLo);
    const unsigned bH = (unsigned)__cvta_generic_to_shared(bHi);
    const unsigned bL = (unsigned)__cvta_generic_to_shared(bLo);

    const int arow = wm + (lane & 15);
    const int lhi  = lane >> 4;

    float c_[4][4] = {};

    #pragma unroll
    for (int ks = 0; ks < 4; ks++) {
        const int cb = (ks << 1) + lhi;
        unsigned a_hi[4], a_lo[4];
        ldsm4(a_hi, aH + sw_off(arow, cb));
        ldsm4(a_lo, aL + sw_off(arow, cb));
        unsigned b_hi[2][4], b_lo[2][4];
        #pragma unroll
        for (int h = 0; h < 2; h++) {
            int brow = wn + (h << 4) + (lane & 15);
            ldsm4(b_hi[h], bH + sw_off(brow, cb));
            ldsm4(b_lo[h], bL + sw_off(brow, cb));
        }
        #pragma unroll
        for (int j = 0; j < 4; j++) {
            const int h = j >> 1, o = j & 1;
            unsigned bh[2] = {b_hi[h][o], b_hi[h][o + 2]};
            unsigned bl[2] = {b_lo[h][o], b_lo[h][o + 2]};
            mma_bf16(c_[j], a_hi, bh);
            mma_bf16(c_[j], a_hi, bl);
            mma_bf16(c_[j], a_lo, bh);
        }
    }

    const int row0 = wm + (lane >> 2);
    const int coll = (lane & 3) << 1;
    #pragma unroll
    for (int j = 0; j < 4; j++) {
        int col = k0 + wn + (j << 3) + coll;
        *(unsigned*)&g_bias[((size_t)row0 << 20) + ((size_t)q << 10) + col] =
            pk_bf2(c_[j][0] * 0.125f, c_[j][1] * 0.125f);
        *(unsigned*)&g_bias[((size_t)(row0 + 8) << 20) + ((size_t)q << 10) + col] =
            pk_bf2(c_[j][2] * 0.125f, c_[j][3] * 0.125f);
    }
}

// ---------------------------------------------------------------------------
// Kernel 2: per (b, 32-row q strip). 512 threads, ~222 KB smem. (R15, control)
// ---------------------------------------------------------------------------
__global__ void __launch_bounds__(512) k_attn(const float* __restrict__ Q,
                                              float* attn,
                                              float* __restrict__ out)
{
    extern __shared__ float sm[];
    float* strip = sm;                                      // [32][1028] fp32
    __nv_bfloat16* pHi = (__nv_bfloat16*)sm;                // after convert
    __nv_bfloat16* pLo = (__nv_bfloat16*)sm + 32768;
    __nv_bfloat16* bufs = (__nv_bfloat16*)(sm + 32 * STRIP);
    __nv_bfloat16* qHi = bufs;
    __nv_bfloat16* qLo = bufs + 2048;
    float* red = (float*)(bufs + 32768);
    __nv_bfloat16* sBias = bufs + 36864;
    __shared__ float sInv[32];

    const int b   = blockIdx.x;
    const int q0  = (gridDim.y - 1 - blockIdx.y) << 5;
    const int tid = threadIdx.x;
    const int warp = tid >> 5, lane = tid & 31, lhi = lane >> 4;

    const unsigned bufsA = (unsigned)__cvta_generic_to_shared(bufs);
    const unsigned sBiasA = (unsigned)__cvta_generic_to_shared(sBias);

    {
        int r = tid >> 4, c = (tid & 15) << 2;
        float4 v = *(const float4*)&Q[((size_t)b << 16) + ((size_t)(q0 + r) << 6) + c];
        split_store(qHi, qLo, r, c, v);
    }
    __syncthreads();

    const unsigned qH = (unsigned)__cvta_generic_to_shared(qHi);
    const unsigned qL = (unsigned)__cvta_generic_to_shared(qLo);

    const int wm1 = (warp & 1) << 4;
    const int wn1 = (warp >> 1) << 4;
    const int ntile1 = (q0 + 32 + 127) >> 7;

    unsigned qfh[4][4], qfl[4][4];
    {
        const int arow = wm1 + (lane & 15);
        #pragma unroll
        for (int ks = 0; ks < 4; ks++) {
            const int cb = (ks << 1) + lhi;
            ldsm4(qfh[ks], qH + sw_off(arow, cb));
            ldsm4(qfl[ks], qL + sw_off(arow, cb));
        }
    }

    auto load_k = [&](int kt) {
        const int p  = kt & 1;
        const int k0 = kt << 7;
        int nrow = q0 + 32 - k0; if (nrow > 128) nrow = 128;
        const int n16 = nrow << 3;
        const uint4* gh = (const uint4*)(g_Khi + ((size_t)b << 16) + ((size_t)k0 << 6));
        const uint4* gl = (const uint4*)(g_Klo + ((size_t)b << 16) + ((size_t)k0 << 6));
        const unsigned sh = bufsA + 8192 + (p << 15);
        const unsigned sl = sh + 16384;
        #pragma unroll
        for (int i = 0; i < 2; i++) {
            int f = tid + (i << 9);
            if (f < n16) {
                cp16(sh + (f << 4), gh + f);
                cp16(sl + (f << 4), gl + f);
            }
        }
        {
            int row = tid >> 4, cb = tid & 15;
            cp16(sBiasA + ((p * 4352 + row * 136 + (cb << 3)) << 1),
                 g_bias + ((size_t)b << 20) + ((size_t)(q0 + row) << 10) + k0 + (cb << 3));
        }
        CP_COMMIT();
    };

    load_k(0);
    for (int kt = 0; kt < ntile1; kt++) {
        const int p  = kt & 1;
        const int k0 = kt << 7;
        const bool more = (kt + 1 < ntile1);
        if (more) load_k(kt + 1);
        if (more) { CP_WAIT1(); } else { CP_WAIT0(); }
        __syncthreads();

        const unsigned kHp = bufsA + 8192 + (p << 15);
        const unsigned kLp = kHp + 16384;
        const bool act1 = (k0 + wn1) <= (q0 + wm1 + 15);
        float c_[2][4] = {};
        if (act1) {
            const int brow = wn1 + (lane & 15);
            #pragma unroll
            for (int ks = 0; ks < 4; ks++) {
                const int cb = (ks << 1) + lhi;
                unsigned b_hi[4], b_lo[4];
                ldsm4(b_hi, kHp + sw_off(brow, cb));
                ldsm4(b_lo, kLp + sw_off(brow, cb));
                #pragma unroll
                for (int j = 0; j < 2; j++) {
                    unsigned bh[2] = {b_hi[j], b_hi[j + 2]};
                    unsigned bl[2] = {b_lo[j], b_lo[j + 2]};
                    mma_bf16(c_[j], qfh[ks], bh);
                    mma_bf16(c_[j], qfh[ks], bl);
                    mma_bf16(c_[j], qfl[ks], bh);
                }
            }
        }
        const int row0 = wm1 + (lane >> 2);
        const int coll = (lane & 3) << 1;
        const int bb = p * 4352;
        if (act1) {
            #pragma unroll
            for (int j = 0; j < 2; j++) {
                int cloc = wn1 + (j << 3) + coll;
                int colk = k0 + cloc;
                {
                    int qr = q0 + row0;
                    float2 bs = bf2f(*(const unsigned*)&sBias[bb + row0 * 136 + cloc]);
                    float s0 = (colk     <= qr) ? fmaf(c_[j][0], 0.125f, bs.x) : 0.f;
                    float s1 = (colk + 1 <= qr) ? fmaf(c_[j][1], 0.125f, bs.y) : 0.f;
                    *(float2*)&strip[row0 * STRIP + colk] = make_float2(s0, s1);
                }
                {
                    int qr = q0 + row0 + 8;
                    float2 bs = bf2f(*(const unsigned*)&sBias[bb + (row0 + 8) * 136 + cloc]);
                    float s0 = (colk     <= qr) ? fmaf(c_[j][2], 0.125f, bs.x) : 0.f;
                    float s1 = (colk + 1 <= qr) ? fmaf(c_[j][3], 0.125f, bs.y) : 0.f;
                    *(float2*)&strip[(row0 + 8) * STRIP + colk] = make_float2(s0, s1);
                }
            }
        } else {
            #pragma unroll
            for (int j = 0; j < 2; j++) {
                int colk = k0 + wn1 + (j << 3) + coll;
                *(float2*)&strip[row0 * STRIP + colk]       = make_float2(0.f, 0.f);
                *(float2*)&strip[(row0 + 8) * STRIP + colk] = make_float2(0.f, 0.f);
            }
        }
        __syncthreads();
    }

    // ---- phase 2: softmax per row ----
    {
        #pragma unroll
        for (int r = 0; r < 2; r++) {
            int row = (warp << 1) + r;
            int qr  = q0 + row;
            float m = -1e30f;
            for (int kk = lane; kk <= qr; kk += 32)
                m = fmaxf(m, strip[row * STRIP + kk]);
            #pragma unroll
            for (int o = 16; o; o >>= 1)
                m = fmaxf(m, __shfl_xor_sync(0xffffffffu, m, o));
            float ssum = 0.f;
            for (int kk = lane; kk <= qr; kk += 32) {
                float e = fast_exp(strip[row * STRIP + kk] - m);
                strip[row * STRIP + kk] = e;
                ssum += e;
            }
            #pragma unroll
            for (int o = 16; o; o >>= 1)
                ssum += __shfl_xor_sync(0xffffffffu, ssum, o);
            if (lane == 0) sInv[row] = 1.0f / ssum;
        }
    }
    __syncthreads();

    // ---- stage/convert: write attn AND convert strip -> split-P in place ----
    {
        float4 vreg[16];
        #pragma unroll
        for (int i = 0; i < 16; i++) {
            int f = tid + (i << 9);
            int row = f >> 8, kc = (f & 255) << 2;
            vreg[i] = *(const float4*)&strip[row * STRIP + kc];
        }
        __syncthreads();
        #pragma unroll
        for (int i = 0; i < 16; i++) {
            int f = tid + (i << 9);
            int row = f >> 8, kc = (f & 255) << 2;
            int qr  = q0 + row;
            float inv = sInv[row];
            float4 e = vreg[i];
            float4 o;
            o.x = (kc     <= qr) ? e.x * inv : 0.f;
            o.y = (kc + 1 <= qr) ? e.y * inv : 0.f;
            o.z = (kc + 2 <= qr) ? e.z * inv : 0.f;
            o.w = (kc + 3 <= qr) ? e.w * inv : 0.f;
            *(float4*)&attn[((size_t)b << 20) + ((size_t)qr << 10) + kc] = o;
            int t = kc >> 6;
            split_store(pHi + (t << 11), pLo + (t << 11), row, kc & 63, e);
        }
    }

    // ---- phase 4: out = P @ V ----
    const int wm4 = (warp & 1) << 4;
    const int wn4 = ((warp >> 1) & 3) << 4;
    const int kg  = warp >> 3;
    const int ntile4 = (q0 + 32 + 127) >> 7;
    const unsigned pH = (unsigned)__cvta_generic_to_shared(pHi);
    const unsigned pL = (unsigned)__cvta_generic_to_shared(pLo);

    auto load_v = [&](int kt) {
        const int p  = kt & 1;
        const int k0 = kt << 7;
        int nrow = q0 + 32 - k0; if (nrow > 128) nrow = 128;
        const int n16 = nrow << 3;
        const uint4* gh = (const uint4*)(g_Vhi + ((size_t)b << 16) + ((size_t)k0 << 6));
        const uint4* gl = (const uint4*)(g_Vlo + ((size_t)b << 16) + ((size_t)k0 << 6));
        const unsigned sh = bufsA + (p << 15);
        const unsigned sl = sh + 16384;
        #pragma unroll
        for (int i = 0; i < 2; i++) {
            int f = tid + (i << 9);
            if (f < n16) {
                cp16(sh + (f << 4), gh + f);
                cp16(sl + (f << 4), gl + f);
            }
        }
        CP_COMMIT();
    };

    float c4[2][4] = {};

    load_v(0);
    for (int kt = 0; kt < ntile4; kt++) {
        const int p  = kt & 1;
        const int k0 = kt << 7;
        const bool more = (kt + 1 < ntile4);
        if (more) load_v(kt + 1);
        if (more) { CP_WAIT1(); } else { CP_WAIT0(); }
        __syncthreads();

        const unsigned vHp = bufsA + (p << 15);
        const unsigned vLp = vHp + 16384;
        const bool act4 = (k0 + (kg << 6)) <= (q0 + 31);
        if (act4) {
            const int arow = wm4 + (lane & 15);
            #pragma unroll
            for (int ks = 0; ks < 4; ks++) {
                const int gk = k0 + (kg << 6) + (ks << 4);
                const int t  = gk >> 6;
                const int cbb = (gk & 63) >> 3;
                unsigned a_hi[4], a_lo[4];
                ldsm4(a_hi, pH + (t << 12) + sw_off(arow, cbb + lhi));
                ldsm4(a_lo, pL + (t << 12) + sw_off(arow, cbb + lhi));
                unsigned b_hi[4], b_lo[4];
                const int brow = (gk - k0) + (lane & 15);
                const int bcb = (wn4 >> 3) + lhi;
                ldsm4t(b_hi, vHp + sw_off(brow, bcb));
                ldsm4t(b_lo, vLp + sw_off(brow, bcb));
                #pragma unroll
                for (int j = 0; j < 2; j++) {
                    unsigned bh[2] = {b_hi[j << 1], b_hi[(j << 1) + 1]};
                    unsigned bl[2] = {b_lo[j << 1], b_lo[(j << 1) + 1]};
                    mma_bf16(c4[j], a_hi, bh);
                    mma_bf16(c4[j], a_hi, bl);
                    mma_bf16(c4[j], a_lo, bh);
                }
            }
        }
        __syncthreads();
    }

    const int row0 = wm4 + (lane >> 2);
    const int coll = (lane & 3) << 1;
    if (kg == 1) {
        #pragma unroll
        for (int j = 0; j < 2; j++) {
            int col = wn4 + (j << 3) + coll;
            *(float2*)&red[(row0 << 6) + col] = make_float2(c4[j][0], c4[j][1]);
            *(float2*)&red[((row0 + 8) << 6) + col] = make_float2(c4[j][2], c4[j][3]);
        }
    }
    __syncthreads();
    if (kg == 0) {
        const float inv0 = sInv[row0];
        const float inv1 = sInv[row0 + 8];
        #pragma unroll
        for (int j = 0; j < 2; j++) {
            int col = wn4 + (j << 3) + coll;
            float2 p0 = *(const float2*)&red[(row0 << 6) + col];
            float2 p1 = *(const float2*)&red[((row0 + 8) << 6) + col];
            *(float2*)&out[((size_t)b << 16) + ((size_t)(q0 + row0) << 6) + col] =
                make_float2((c4[j][0] + p0.x) * inv0, (c4[j][1] + p0.y) * inv0);
            *(float2*)&out[((size_t)b << 16) + ((size_t)(q0 + row0 + 8) << 6) + col] =
                make_float2((c4[j][2] + p1.x) * inv1, (c4[j][3] + p1.y) * inv1);
        }
    }
}

// ---------------------------------------------------------------------------
// Kernel 3: out[b,q,d] += sum_k attn[b,q,k] * R_v[q,k,d]
// NEW: cp.async double-buffered fp32 staging + convert pass. 256 thr, 96 KB.
// ---------------------------------------------------------------------------
__global__ void __launch_bounds__(256) k_rv(const float* __restrict__ attn,
                                            const float* __restrict__ Rv,
                                            float* __restrict__ out)
{
    extern __shared__ float dsm[];
    float* aStage = dsm;                    // 2 x 4096 fp32
    float* rStage = dsm + 8192;             // 2 x 4096 fp32
    __nv_bfloat16* aHi = (__nv_bfloat16*)(dsm + 16384);
    __nv_bfloat16* aLo = aHi + 4096;
    __nv_bfloat16* bHi = aHi + 8192;
    __nv_bfloat16* bLo = aHi + 12288;

    const int q   = 1023 - blockIdx.x;
    const int tid = threadIdx.x;
    const int ntile = (q >> 6) + 1;

    const unsigned aStA = (unsigned)__cvta_generic_to_shared(aStage);
    const unsigned rStA = (unsigned)__cvta_generic_to_shared(rStage);

    auto load_t = [&](int kt) {
        const int p  = kt & 1;
        const int k0 = kt << 6;
        #pragma unroll
        for (int i = 0; i < 4; i++) {
            int f = tid + (i << 8);       // 1024 uint4 per array
            int r = f >> 4, c4 = (f & 15) << 2;
            cp16(aStA + ((p << 12) + f * 4) * 4,
                 attn + ((size_t)r << 20) + ((size_t)q << 10) + k0 + c4);
            cp16(rStA + ((p << 12) + f * 4) * 4,
                 Rv + (((size_t)q << 10) + (size_t)(k0 + r)) * 64 + c4);
        }
        CP_COMMIT();
    };

    const int warp = tid >> 5, lane = tid & 31;
    const int wm = (warp & 3) << 4;
    const int wn = (warp >> 2) << 5;

    const unsigned aH = (unsigned)__cvta_generic_to_shared(aHi);
    const unsigned aL = (unsigned)__cvta_generic_to_shared(aLo);
    const unsigned bH = (unsigned)__cvta_generic_to_shared(bHi);
    const unsigned bL = (unsigned)__cvta_generic_to_shared(bLo);

    const int arow = wm + (lane & 15);
    const int lhi  = lane >> 4;

    float c_[4][4] = {};

    load_t(0);
    for (int kt = 0; kt < ntile; kt++) {
        const int p = kt & 1;
        const bool more = (kt + 1 < ntile);
        if (more) load_t(kt + 1);
        if (more) { CP_WAIT1(); } else { CP_WAIT0(); }
        __syncthreads();                       // stage[p] ready; prev mma done

        // convert stage -> split buffers
        #pragma unroll
        for (int i = 0; i < 4; i++) {
            int f = tid + (i << 8);
            int r = f >> 4, c = (f & 15) << 2;
            float4 va = *(const float4*)&aStage[(p << 12) + (r << 6) + c];
            float4 vr = *(const float4*)&rStage[(p << 12) + (r << 6) + c];
            split_store(aHi, aLo, r, c, va);
            split_store(bHi, bLo, r, c, vr);
        }
        __syncthreads();

        #pragma unroll
        for (int ks = 0; ks < 4; ks++) {
            const int cb = (ks << 1) + lhi;
            unsigned a_hi[4], a_lo[4];
            ldsm4(a_hi, aH + sw_off(arow, cb));
            ldsm4(a_lo, aL + sw_off(arow, cb));
            unsigned b_hi[2][4], b_lo[2][4];
            #pragma unroll
            for (int h = 0; h < 2; h++) {
                int brow = (ks << 4) + (lane & 15);
                int bcb  = ((wn + (h << 4)) >> 3) + lhi;
                ldsm4t(b_hi[h], bH + sw_off(brow, bcb));
                ldsm4t(b_lo[h], bL + sw_off(brow, bcb));
            }
            #pragma unroll
            for (int j = 0; j < 4; j++) {
                const int h = j >> 1, o = j & 1;
                unsigned bh[2] = {b_hi[h][o << 1], b_hi[h][(o << 1) + 1]};
                unsigned bl[2] = {b_lo[h][o << 1], b_lo[h][(o << 1) + 1]};
                mma_bf16(c_[j], a_hi, bh);
                mma_bf16(c_[j], a_hi, bl);
                mma_bf16(c_[j], a_lo, bh);
            }
        }
    }

    const int row0 = wm + (lane >> 2);
    const int coll = (lane & 3) << 1;
    #pragma unroll
    for (int j = 0; j < 4; j++) {
        int col = wn + (j << 3) + coll;
        {
            float2* p = (float2*)&out[((size_t)row0 << 16) + ((size_t)q << 6) + col];
            float2 o = *p; o.x += c_[j][0]; o.y += c_[j][1]; *p = o;
        }
        {
            float2* p = (float2*)&out[((size_t)(row0 + 8) << 16) + ((size_t)q << 6) + col];
            float2 o = *p; o.x += c_[j][2]; o.y += c_[j][3]; *p = o;
        }
    }
}

// ---------------------------------------------------------------------------
extern "C" void kernel_launch(void* const* d_in, const int* in_sizes, int n_in,
                              void* d_out, int out_size)
{
    const float* Q  = (const float*)d_in[0];
    const float* K  = (const float*)d_in[1];
    const float* V  = (const float*)d_in[2];
    const float* Rk = (const float*)d_in[3];
    const float* Rv = (const float*)d_in[4];
    float* out  = (float*)d_out;
    float* attn = out + SZ_OUT;

    const int smem2 = 32 * STRIP * (int)sizeof(float)
                    + 36864 * (int)sizeof(__nv_bfloat16)
                    + 8704 * (int)sizeof(__nv_bfloat16);
    cudaFuncSetAttribute(k_attn, cudaFuncAttributeMaxDynamicSharedMemorySize, smem2);

    // k_rv: stage 2x(16K+16K) + split 32K = 96 KB
    const int smem3 = 98304;
    cudaFuncSetAttribute(k_rv, cudaFuncAttributeMaxDynamicSharedMemorySize, smem3);

    k_prep<<<dim3(64, 8), 256>>>(K, V);
    k_bias<<<dim3(16, 1024), 256>>>(Q, Rk);
    k_attn<<<dim3(64, 32), 512, smem2>>>(Q, attn, out);
    k_rv<<<1024, 256, smem3>>>(attn, Rv, out);
}